// round 5
// baseline (speedup 1.0000x reference)
#include <cuda_runtime.h>
#include <cfloat>
#include <cstdint>

// Problem: V [1024, 8192] fp32 -> out [1024, 8192] fp32
#define Mm    8192
#define Nn    1024
#define STEPS 8192          // 8 rounds * 1024 rows
#define C     8             // cluster CTAs
#define TPB   256           // 8 warps per CTA
#define W     8             // warps per CTA
#define K     4             // columns per thread  (C*TPB*K == Mm)
#define NSLOT (C*W)         // 64 publishers cluster-wide
#define LOG2E 1.4426950408889634f

__device__ float g_rmin[Nn];

// ---------------------------------------------------------------------------
__global__ void softrr_init(const float* __restrict__ V) {
    const int b = blockIdx.x, t = threadIdx.x;
    const float* row = V + (size_t)b * Mm;
    float mn = FLT_MAX;
    for (int j = t; j < Mm; j += 256) mn = fminf(mn, row[j]);
    #pragma unroll
    for (int o = 16; o; o >>= 1) mn = fminf(mn, __shfl_down_sync(0xffffffffu, mn, o));
    __shared__ float s[8];
    if ((t & 31) == 0) s[t >> 5] = mn;
    __syncthreads();
    if (t == 0) {
        float r = s[0];
        #pragma unroll
        for (int w = 1; w < 8; w++) r = fminf(r, s[w]);
        g_rmin[b] = r;
    }
}

// ------------------------- primitives --------------------------------------
__device__ __forceinline__ void ld_vol_v4(uint32_t a, float4& f) {
    asm volatile("ld.volatile.shared.v4.f32 {%0,%1,%2,%3}, [%4];"
                 : "=f"(f.x), "=f"(f.y), "=f"(f.z), "=f"(f.w) : "r"(a));
}
__device__ __forceinline__ uint32_t mapa_rank(uint32_t local_addr, int rank) {
    uint32_t ra;
    asm volatile("mapa.shared::cluster.u32 %0, %1, %2;" : "=r"(ra) : "r"(local_addr), "r"(rank));
    return ra;
}
__device__ __forceinline__ void st_cluster_f32(uint32_t ra, float v) {
    asm volatile("st.shared::cluster.f32 [%0], %1;" :: "r"(ra), "f"(v) : "memory");
}
__device__ __forceinline__ float ex2(float z) {
    float e; asm("ex2.approx.f32 %0, %1;" : "=f"(e) : "f"(z));
    return e;
}
__device__ __forceinline__ float rcp(float x) {
    float r; asm("rcp.approx.f32 %0, %1;" : "=f"(r) : "f"(x));
    return r;
}

// ---------------------------------------------------------------------------
// ONE cluster: 8 CTAs x 256 threads x 4 cols/thread. Barrier-free scan with
// exactly TWO reduction levels and ONE DSMEM hop per step:
//   level 1 (producer): each warp xor-butterflies its 32 col-sums (all lanes
//            get p, identical tree); lanes 0-7 push  sign*p  directly into
//            slot[ph][rank*8+wid] of ALL 8 CTAs (remote addrs precomputed).
//   level 2 (consumer): every warp polls its LOCAL 64 slots (lane i -> quad
//            i&15, ld.volatile.v4), serial-sums 4, xor-butterflies 4 levels.
//            xor-butterfly = same add-tree in every lane (fp add commutes
//            bit-exactly) -> S is bit-identical in every lane/warp/CTA.
// Ring depth 2 with sign parity ((r>>1)&1): stale data has wrong sign, so no
// zeroing and no barriers anywhere in the loop.
// ---------------------------------------------------------------------------
__global__ void __launch_bounds__(TPB, 1) __cluster_dims__(C, 1, 1)
softrr_main(const float* __restrict__ V, float* __restrict__ out) {
    __shared__ float s_rmin[Nn];
    __shared__ __align__(16) float s_slot[2 * NSLOT];   // [phase][publisher]

    const int tid  = threadIdx.x;
    const int lane = tid & 31;
    const int wid  = tid >> 5;
    const int rank = blockIdx.x;
    const int col0 = rank * (TPB * K) + tid;             // cols: col0 + k*TPB

    const uint32_t slot_base = (uint32_t)__cvta_generic_to_shared(s_slot);

    // precompute this lane's remote slot address (phase 0); +NSLOT*4 for ph1
    uint32_t ra0 = 0;
    if (lane < C)
        ra0 = mapa_rank(slot_base, lane) + (uint32_t)(rank * W + wid) * 4u;

    if (tid < 2 * NSLOT) s_slot[tid] = 0.0f;
    #pragma unroll
    for (int i = 0; i < Nn / TPB; i++) s_rmin[i * TPB + tid] = g_rmin[i * TPB + tid];
    __syncthreads();
    asm volatile("barrier.cluster.arrive.aligned;" ::: "memory");
    asm volatile("barrier.cluster.wait.aligned;"   ::: "memory");

    float c[K], a2[K], o_acc[K], a2n[K], o_nx[K];
    #pragma unroll
    for (int k = 0; k < K; k++) {
        c[k]     = 1.0f;
        a2[k]    = (V[col0 + k * TPB] - s_rmin[0] + 1.0f) * LOG2E;  // row 0
        o_acc[k] = 0.0f;                                            // round 0 overwrites
    }

    // consumer quad address (local): lane i reads quad (i & 15)
    const uint32_t qa0 = slot_base + (uint32_t)(lane & 15) * 16u;

    for (int r = 0; r < STEPS; r++) {
        const int  ph  = r & 1;
        const bool neg = (r >> 1) & 1;

        // --- level 1: per-warp reduce + direct DSMEM publish
        float e[K];
        #pragma unroll
        for (int k = 0; k < K; k++) e[k] = ex2(a2[k] * c[k]);
        float p = (e[0] + e[1]) + (e[2] + e[3]);
        #pragma unroll
        for (int o = 16; o; o >>= 1) p += __shfl_xor_sync(0xffffffffu, p, o);
        if (lane < C)
            st_cluster_f32(ra0 + (uint32_t)(ph * NSLOT) * 4u, neg ? -p : p);

        // --- latency slack: prefetch next row's V / out
        if (r + 1 < STEPS) {
            const int rn = (r + 1) & (Nn - 1);
            const float rm = s_rmin[rn];
            #pragma unroll
            for (int k = 0; k < K; k++) {
                a2n[k] = (V[(size_t)rn * Mm + col0 + k * TPB] - rm + 1.0f) * LOG2E;
                o_nx[k] = (r + 1 >= Nn) ? out[(size_t)rn * Mm + col0 + k * TPB] : 0.0f;
            }
        }

        // --- level 2: every warp polls local slots, reduces to S
        const uint32_t qa = qa0 + (uint32_t)(ph * NSLOT) * 4u;
        float4 A; bool ok;
        do {
            ld_vol_v4(qa, A);
            if (neg) ok = (A.x < 0.f) & (A.y < 0.f) & (A.z < 0.f) & (A.w < 0.f);
            else     ok = (A.x > 0.f) & (A.y > 0.f) & (A.z > 0.f) & (A.w > 0.f);
        } while (!ok);
        float S = (fabsf(A.x) + fabsf(A.y)) + (fabsf(A.z) + fabsf(A.w));
        #pragma unroll
        for (int o = 8; o; o >>= 1) S += __shfl_xor_sync(0xffffffffu, S, o);

        // --- epilogue
        const float rinv = rcp(S);
        const int   row  = r & (Nn - 1);
        #pragma unroll
        for (int k = 0; k < K; k++) {
            const float y = e[k] * rinv;
            out[(size_t)row * Mm + col0 + k * TPB] = o_acc[k] + y;
            c[k]     = __fmaf_rn(-y, c[k], c[k]);
            a2[k]    = a2n[k];
            o_acc[k] = o_nx[k];
        }
    }
}

extern "C" void kernel_launch(void* const* d_in, const int* in_sizes, int n_in,
                              void* d_out, int out_size) {
    const float* V = (const float*)d_in[0];
    float* out = (float*)d_out;
    (void)in_sizes; (void)n_in; (void)out_size;

    softrr_init<<<Nn, 256>>>(V);
    softrr_main<<<C, TPB>>>(V, out);
}

// round 6
// speedup vs baseline: 2.9057x; 2.9057x over previous
#include <cuda_runtime.h>
#include <cfloat>
#include <cstdint>

// Problem: V [1024, 8192] fp32 -> out [1024, 8192] fp32
#define Mm    8192
#define Nn    1024
#define STEPS 8192          // 8 rounds * 1024 rows
#define C     8             // cluster CTAs
#define TPB   128           // 4 warps per CTA (1 per SMSP)
#define W     4             // warps per CTA
#define K     8             // columns per thread  (C*TPB*K == Mm)
#define LOG2E 1.4426950408889634f

__device__ float g_rmin[Nn];

// ---------------------------------------------------------------------------
__global__ void softrr_init(const float* __restrict__ V) {
    const int b = blockIdx.x, t = threadIdx.x;
    const float* row = V + (size_t)b * Mm;
    float mn = FLT_MAX;
    for (int j = t; j < Mm; j += 256) mn = fminf(mn, row[j]);
    #pragma unroll
    for (int o = 16; o; o >>= 1) mn = fminf(mn, __shfl_down_sync(0xffffffffu, mn, o));
    __shared__ float s[8];
    if ((t & 31) == 0) s[t >> 5] = mn;
    __syncthreads();
    if (t == 0) {
        float r = s[0];
        #pragma unroll
        for (int w = 1; w < 8; w++) r = fminf(r, s[w]);
        g_rmin[b] = r;
    }
}

// ------------------------- primitives --------------------------------------
__device__ __forceinline__ void ld_vol_v4(uint32_t a, float4& f) {
    asm volatile("ld.volatile.shared.v4.f32 {%0,%1,%2,%3}, [%4];"
                 : "=f"(f.x), "=f"(f.y), "=f"(f.z), "=f"(f.w) : "r"(a));
}
__device__ __forceinline__ void st_vol_f32(uint32_t a, float v) {
    asm volatile("st.volatile.shared.f32 [%0], %1;" :: "r"(a), "f"(v) : "memory");
}
__device__ __forceinline__ uint32_t mapa_rank(uint32_t local_addr, int rank) {
    uint32_t ra;
    asm volatile("mapa.shared::cluster.u32 %0, %1, %2;" : "=r"(ra) : "r"(local_addr), "r"(rank));
    return ra;
}
__device__ __forceinline__ void st_cluster_f32(uint32_t ra, float v) {
    asm volatile("st.shared::cluster.f32 [%0], %1;" :: "r"(ra), "f"(v) : "memory");
}
__device__ __forceinline__ float ex2(float z) {
    float e; asm("ex2.approx.f32 %0, %1;" : "=f"(e) : "f"(z));
    return e;
}
__device__ __forceinline__ float rcp(float x) {
    float r; asm("rcp.approx.f32 %0, %1;" : "=f"(r) : "f"(x));
    return r;
}

// ---------------------------------------------------------------------------
// ONE cluster: 8 CTAs x 128 threads (4 warps, 1 per SMSP) x 8 cols/thread.
// Per step r (phase ph=r&1, sign parity neg=(r>>1)&1):
//   all warps : e_k = 2^(a2_k*c_k); esum = fixed pairwise tree of 8;
//               p = xor-butterfly(32) [identical tree in every lane];
//               lane0 STS ±p -> s_wp[ph][wid]            (4 slots)
//   warp 0    : UNIFORM poll of the one s_wp quad (broadcast ld.volatile.v4,
//               plain sign checks — no ballot), P = fixed sum of 4 |.|,
//               lanes 0-7 push ±P into slot[ph][rank] of ALL 8 CTAs
//               (mapa addresses hoisted).                (8 msgs/CTA, 64 total)
//   all warps : UNIFORM poll of 2 local slot quads, S = fixed ILP tree of
//               8 |.|  -> bit-identical in every lane/warp/CTA.
//   epilogue  : rinv=rcp(S); y=e*rinv; out+=y; c=fma(-y,c,c).
// Depth-2 rings with sign parity: stale data has the wrong sign -> no
// zeroing, no __syncthreads anywhere in the loop.
// ---------------------------------------------------------------------------
__global__ void __launch_bounds__(TPB, 1) __cluster_dims__(C, 1, 1)
softrr_main(const float* __restrict__ V, float* __restrict__ out) {
    __shared__ float s_rmin[Nn];
    __shared__ __align__(16) float s_wp[2 * W];      // [phase][warp]   1 quad/phase
    __shared__ __align__(16) float s_slot[2 * C];    // [phase][rank]   2 quads/phase

    const int tid  = threadIdx.x;
    const int lane = tid & 31;
    const int wid  = tid >> 5;
    const int rank = blockIdx.x;
    const int col0 = rank * (TPB * K) + tid;          // cols: col0 + k*TPB

    const uint32_t wp_base   = (uint32_t)__cvta_generic_to_shared(s_wp);
    const uint32_t slot_base = (uint32_t)__cvta_generic_to_shared(s_slot);

    // hoisted remote slot address (phase 0); add C*4 bytes for phase 1
    uint32_t ra0 = 0;
    if (wid == 0 && lane < C)
        ra0 = mapa_rank(slot_base, lane) + (uint32_t)rank * 4u;

    if (tid < 2 * W)  s_wp[tid]   = 0.0f;
    if (tid < 2 * C)  s_slot[tid] = 0.0f;
    #pragma unroll
    for (int i = 0; i < Nn / TPB; i++) s_rmin[i * TPB + tid] = g_rmin[i * TPB + tid];
    __syncthreads();
    asm volatile("barrier.cluster.arrive.aligned;" ::: "memory");
    asm volatile("barrier.cluster.wait.aligned;"   ::: "memory");

    float c[K], a2[K], o_acc[K], a2n[K], o_nx[K];
    #pragma unroll
    for (int k = 0; k < K; k++) {
        c[k]     = 1.0f;
        a2[k]    = (V[col0 + k * TPB] - s_rmin[0] + 1.0f) * LOG2E;  // row 0
        o_acc[k] = 0.0f;                                            // round 0 overwrites
    }

    for (int r = 0; r < STEPS; r++) {
        const int  ph  = r & 1;
        const bool neg = (r >> 1) & 1;

        // --- produce: 8 exps, pairwise tree, warp butterfly, STS relay
        float e[K];
        #pragma unroll
        for (int k = 0; k < K; k++) e[k] = ex2(a2[k] * c[k]);
        float p = ((e[0] + e[1]) + (e[2] + e[3])) + ((e[4] + e[5]) + (e[6] + e[7]));
        #pragma unroll
        for (int o = 16; o; o >>= 1) p += __shfl_xor_sync(0xffffffffu, p, o);
        if (lane == 0)
            st_vol_f32(wp_base + (uint32_t)(ph * W + wid) * 4u, neg ? -p : p);

        // --- warp0 relay: uniform 1-quad poll (no ballot), fixed sum, publish
        if (wid == 0) {
            const uint32_t wa = wp_base + (uint32_t)(ph * W) * 4u;
            float4 Wv; bool ok;
            do {
                ld_vol_v4(wa, Wv);
                if (neg) ok = (Wv.x < 0.f) & (Wv.y < 0.f) & (Wv.z < 0.f) & (Wv.w < 0.f);
                else     ok = (Wv.x > 0.f) & (Wv.y > 0.f) & (Wv.z > 0.f) & (Wv.w > 0.f);
            } while (!ok);
            const float P = (fabsf(Wv.x) + fabsf(Wv.y)) + (fabsf(Wv.z) + fabsf(Wv.w));
            if (lane < C)
                st_cluster_f32(ra0 + (uint32_t)(ph * C) * 4u, neg ? -P : P);
        }

        // --- latency slack: prefetch next row's V / out (overlaps DSMEM flight)
        if (r + 1 < STEPS) {
            const int rn = (r + 1) & (Nn - 1);
            const float rm = s_rmin[rn];
            #pragma unroll
            for (int k = 0; k < K; k++) {
                a2n[k] = (V[(size_t)rn * Mm + col0 + k * TPB] - rm + 1.0f) * LOG2E;
                o_nx[k] = (r + 1 >= Nn) ? out[(size_t)rn * Mm + col0 + k * TPB] : 0.0f;
            }
        }

        // --- consume: uniform 2-quad poll of the 8 CTA partials
        const uint32_t sa = slot_base + (uint32_t)(ph * C) * 4u;
        float4 A, B; bool ok;
        do {
            ld_vol_v4(sa,      A);
            ld_vol_v4(sa + 16, B);
            if (neg) ok = (A.x < 0.f) & (A.y < 0.f) & (A.z < 0.f) & (A.w < 0.f) &
                          (B.x < 0.f) & (B.y < 0.f) & (B.z < 0.f) & (B.w < 0.f);
            else     ok = (A.x > 0.f) & (A.y > 0.f) & (A.z > 0.f) & (A.w > 0.f) &
                          (B.x > 0.f) & (B.y > 0.f) & (B.z > 0.f) & (B.w > 0.f);
        } while (!ok);
        const float S = ((fabsf(A.x) + fabsf(A.y)) + (fabsf(A.z) + fabsf(A.w)))
                      + ((fabsf(B.x) + fabsf(B.y)) + (fabsf(B.z) + fabsf(B.w)));

        // --- epilogue
        const float rinv = rcp(S);
        const int   row  = r & (Nn - 1);
        #pragma unroll
        for (int k = 0; k < K; k++) {
            const float y = e[k] * rinv;
            out[(size_t)row * Mm + col0 + k * TPB] = o_acc[k] + y;
            c[k]     = __fmaf_rn(-y, c[k], c[k]);
            a2[k]    = a2n[k];
            o_acc[k] = o_nx[k];
        }
    }
}

extern "C" void kernel_launch(void* const* d_in, const int* in_sizes, int n_in,
                              void* d_out, int out_size) {
    const float* V = (const float*)d_in[0];
    float* out = (float*)d_out;
    (void)in_sizes; (void)n_in; (void)out_size;

    softrr_init<<<Nn, 256>>>(V);
    softrr_main<<<C, TPB>>>(V, out);
}

// round 8
// speedup vs baseline: 2.9225x; 1.0058x over previous
#include <cuda_runtime.h>
#include <cfloat>
#include <cstdint>

// Problem: V [1024, 8192] fp32 -> out [1024, 8192] fp32
#define Mm    8192
#define Nn    1024
#define STEPS 8192          // 8 rounds * 1024 rows
#define C     4             // cluster CTAs (minimize DSMEM egress transactions)
#define TPB   256           // 8 warps per CTA
#define W     8             // warps per CTA
#define K     8             // columns per thread  (C*TPB*K == Mm)
#define LOG2E 1.4426950408889634f

__device__ float g_rmin[Nn];

// ---------------------------------------------------------------------------
__global__ void softrr_init(const float* __restrict__ V) {
    const int b = blockIdx.x, t = threadIdx.x;
    const float* row = V + (size_t)b * Mm;
    float mn = FLT_MAX;
    for (int j = t; j < Mm; j += 256) mn = fminf(mn, row[j]);
    #pragma unroll
    for (int o = 16; o; o >>= 1) mn = fminf(mn, __shfl_down_sync(0xffffffffu, mn, o));
    __shared__ float s[8];
    if ((t & 31) == 0) s[t >> 5] = mn;
    __syncthreads();
    if (t == 0) {
        float r = s[0];
        #pragma unroll
        for (int w = 1; w < 8; w++) r = fminf(r, s[w]);
        g_rmin[b] = r;
    }
}

// ------------------------- primitives --------------------------------------
__device__ __forceinline__ void ld_vol_v4(uint32_t a, float4& f) {
    asm volatile("ld.volatile.shared.v4.f32 {%0,%1,%2,%3}, [%4];"
                 : "=f"(f.x), "=f"(f.y), "=f"(f.z), "=f"(f.w) : "r"(a));
}
__device__ __forceinline__ void st_vol_f32(uint32_t a, float v) {
    asm volatile("st.volatile.shared.f32 [%0], %1;" :: "r"(a), "f"(v) : "memory");
}
__device__ __forceinline__ uint32_t mapa_rank(uint32_t local_addr, int rank) {
    uint32_t ra;
    asm volatile("mapa.shared::cluster.u32 %0, %1, %2;" : "=r"(ra) : "r"(local_addr), "r"(rank));
    return ra;
}
__device__ __forceinline__ void st_cluster_f32(uint32_t ra, float v) {
    asm volatile("st.shared::cluster.f32 [%0], %1;" :: "r"(ra), "f"(v) : "memory");
}
__device__ __forceinline__ float ex2(float z) {
    float e; asm("ex2.approx.f32 %0, %1;" : "=f"(e) : "f"(z));
    return e;
}
__device__ __forceinline__ float rcp(float x) {
    float r; asm("rcp.approx.f32 %0, %1;" : "=f"(r) : "f"(x));
    return r;
}
// xor-butterfly warp sum: identical add-tree in every lane -> uniform result.
__device__ __forceinline__ float warp_sum(float v) {
    #pragma unroll
    for (int o = 16; o; o >>= 1) v += __shfl_xor_sync(0xffffffffu, v, o);
    return v;
}

// ---------------------------------------------------------------------------
// ONE cluster: 4 CTAs x 256 threads (8 warps) x 8 cols/thread.
// Per step r (phase ph=r&1, sign parity neg=(r>>1)&1):
//   all warps : e_k = 2^(a2_k*c_k); p = warp_sum(fixed pairwise tree of 8);
//               lane0 STS ±p -> s_wp[ph][wid]               (8 slots = 2 quads)
//   warp 0    : UNIFORM poll of the 2 s_wp quads (broadcast ld.volatile.v4,
//               plain sign checks), P = fixed serial sum of 8 |.|,
//               lanes 0-3 push ±P into slot[ph][rank] of ALL 4 CTAs
//               (3 remote egress transactions — THE knob this round).
//   all warps : UNIFORM poll of 1 local slot quad, S = fixed sum of 4 |.|
//               -> bit-identical in every lane/warp/CTA.
//   epilogue  : rinv=rcp(S); y=e*rinv; out+=y; c=fma(-y,c,c).
// Depth-2 rings with sign parity: stale data has the wrong sign -> no
// zeroing, no __syncthreads anywhere in the loop.
// ---------------------------------------------------------------------------
__global__ void __launch_bounds__(TPB, 1) __cluster_dims__(C, 1, 1)
softrr_main(const float* __restrict__ V, float* __restrict__ out) {
    __shared__ float s_rmin[Nn];
    __shared__ __align__(16) float s_wp[2 * W];      // [phase][warp]   2 quads/phase
    __shared__ __align__(16) float s_slot[2 * C];    // [phase][rank]   1 quad/phase

    const int tid  = threadIdx.x;
    const int lane = tid & 31;
    const int wid  = tid >> 5;
    const int rank = blockIdx.x;
    const int col0 = rank * (TPB * K) + tid;          // cols: col0 + k*TPB

    const uint32_t wp_base   = (uint32_t)__cvta_generic_to_shared(s_wp);
    const uint32_t slot_base = (uint32_t)__cvta_generic_to_shared(s_slot);

    // hoisted remote slot address (phase 0); add C*4 bytes for phase 1
    uint32_t ra0 = 0;
    if (wid == 0 && lane < C)
        ra0 = mapa_rank(slot_base, lane) + (uint32_t)rank * 4u;

    if (tid < 2 * W) s_wp[tid]   = 0.0f;
    if (tid < 2 * C) s_slot[tid] = 0.0f;
    #pragma unroll
    for (int i = 0; i < Nn / TPB; i++) s_rmin[i * TPB + tid] = g_rmin[i * TPB + tid];
    __syncthreads();
    asm volatile("barrier.cluster.arrive.aligned;" ::: "memory");
    asm volatile("barrier.cluster.wait.aligned;"   ::: "memory");

    float c[K], a2[K], o_acc[K], a2n[K], o_nx[K];
    #pragma unroll
    for (int k = 0; k < K; k++) {
        c[k]     = 1.0f;
        a2[k]    = (V[col0 + k * TPB] - s_rmin[0] + 1.0f) * LOG2E;  // row 0
        o_acc[k] = 0.0f;                                            // round 0 overwrites
    }

    for (int r = 0; r < STEPS; r++) {
        const int  ph  = r & 1;
        const bool neg = (r >> 1) & 1;

        // --- produce: 8 exps, pairwise tree, warp butterfly, STS relay
        float e[K];
        #pragma unroll
        for (int k = 0; k < K; k++) e[k] = ex2(a2[k] * c[k]);
        const float t8 = ((e[0] + e[1]) + (e[2] + e[3])) + ((e[4] + e[5]) + (e[6] + e[7]));
        const float p  = warp_sum(t8);
        if (lane == 0)
            st_vol_f32(wp_base + (uint32_t)(ph * W + wid) * 4u, neg ? -p : p);

        // --- warp0 relay: uniform 2-quad poll (no ballot), fixed sum, publish
        if (wid == 0) {
            const uint32_t wa = wp_base + (uint32_t)(ph * W) * 4u;
            float4 Wa, Wb; bool ok;
            do {
                ld_vol_v4(wa,      Wa);
                ld_vol_v4(wa + 16, Wb);
                if (neg) ok = (Wa.x < 0.f) & (Wa.y < 0.f) & (Wa.z < 0.f) & (Wa.w < 0.f) &
                              (Wb.x < 0.f) & (Wb.y < 0.f) & (Wb.z < 0.f) & (Wb.w < 0.f);
                else     ok = (Wa.x > 0.f) & (Wa.y > 0.f) & (Wa.z > 0.f) & (Wa.w > 0.f) &
                              (Wb.x > 0.f) & (Wb.y > 0.f) & (Wb.z > 0.f) & (Wb.w > 0.f);
            } while (!ok);
            const float P = ((fabsf(Wa.x) + fabsf(Wa.y)) + (fabsf(Wa.z) + fabsf(Wa.w)))
                          + ((fabsf(Wb.x) + fabsf(Wb.y)) + (fabsf(Wb.z) + fabsf(Wb.w)));
            if (lane < C)
                st_cluster_f32(ra0 + (uint32_t)(ph * C) * 4u, neg ? -P : P);
        }

        // --- latency slack: prefetch next row's V / out (overlaps DSMEM flight)
        if (r + 1 < STEPS) {
            const int rn = (r + 1) & (Nn - 1);
            const float rm = s_rmin[rn];
            #pragma unroll
            for (int k = 0; k < K; k++) {
                a2n[k] = (V[(size_t)rn * Mm + col0 + k * TPB] - rm + 1.0f) * LOG2E;
                o_nx[k] = (r + 1 >= Nn) ? out[(size_t)rn * Mm + col0 + k * TPB] : 0.0f;
            }
        }

        // --- consume: uniform 1-quad poll of the 4 CTA partials
        const uint32_t sa = slot_base + (uint32_t)(ph * C) * 4u;
        float4 A; bool ok;
        do {
            ld_vol_v4(sa, A);
            if (neg) ok = (A.x < 0.f) & (A.y < 0.f) & (A.z < 0.f) & (A.w < 0.f);
            else     ok = (A.x > 0.f) & (A.y > 0.f) & (A.z > 0.f) & (A.w > 0.f);
        } while (!ok);
        const float S = (fabsf(A.x) + fabsf(A.y)) + (fabsf(A.z) + fabsf(A.w));

        // --- epilogue
        const float rinv = rcp(S);
        const int   row  = r & (Nn - 1);
        #pragma unroll
        for (int k = 0; k < K; k++) {
            const float y = e[k] * rinv;
            out[(size_t)row * Mm + col0 + k * TPB] = o_acc[k] + y;
            c[k]     = __fmaf_rn(-y, c[k], c[k]);
            a2[k]    = a2n[k];
            o_acc[k] = o_nx[k];
        }
    }
}

extern "C" void kernel_launch(void* const* d_in, const int* in_sizes, int n_in,
                              void* d_out, int out_size) {
    const float* V = (const float*)d_in[0];
    float* out = (float*)d_out;
    (void)in_sizes; (void)n_in; (void)out_size;

    softrr_init<<<Nn, 256>>>(V);
    softrr_main<<<C, TPB>>>(V, out);
}